// round 2
// baseline (speedup 1.0000x reference)
#include <cuda_runtime.h>

#define Bsz 64
#define Ssz 128
#define Fdim 16
#define Hdim 64

typedef unsigned long long u64;

__device__ __forceinline__ u64 pk(float a, float b) {
    u64 r; asm("mov.b64 %0, {%1,%2};" : "=l"(r) : "f"(a), "f"(b)); return r;
}
__device__ __forceinline__ u64 fma2(u64 a, u64 b, u64 c) {
    u64 d; asm("fma.rn.f32x2 %0, %1, %2, %3;" : "=l"(d) : "l"(a), "l"(b), "l"(c)); return d;
}
__device__ __forceinline__ float2 upk(u64 v) {
    float2 r; asm("mov.b64 {%0,%1}, %2;" : "=f"(r.x), "=f"(r.y) : "l"(v)); return r;
}
__device__ __forceinline__ float sigm(float x) { return __fdividef(1.f, 1.f + __expf(-x)); }
__device__ __forceinline__ float tanh_(float x) { return 1.f - __fdividef(2.f, __expf(2.f * x) + 1.f); }

// scratch
__device__ float g_lstm[2u * Bsz * Fdim * Ssz * Hdim];        // [br][b][f][s][h]
__device__ float g_pooled[2u * Bsz * Fdim * Hdim];
__device__ ulonglong2 g_w2k2[32 * 64 * 32];                    // dup-packed k weights [pair][dk][j/2]
__device__ ulonglong2 g_WqTp[32 * 64 * 16];                    // transposed q weights [pair][j][h/4]
__device__ float4 g_qsc4[2048u * 2048];                        // q scratch [pair][qi][h/4]

// ---------------------------------------------------------------------------
// Prep: pre-transform attention in-proj weights.
// ---------------------------------------------------------------------------
__global__ void prep_kernel(const float* __restrict__ wd_aw, const float* __restrict__ rd_aw)
{
    int f = blockIdx.x, br = blockIdx.y, tid = threadIdx.x;
    const float* aw = (br ? rd_aw : wd_aw) + (size_t)f * 192 * 64;
    int pair = br * 16 + f;
    for (int i = tid; i < 2048; i += 256) {          // k weights dup-packed
        int dk = i >> 5, j2 = i & 31;
        float w0 = aw[(64 + dk) * 64 + 2 * j2];
        float w1 = aw[(64 + dk) * 64 + 2 * j2 + 1];
        g_w2k2[((size_t)pair * 64 + dk) * 32 + j2] = make_ulonglong2(pk(w0, w0), pk(w1, w1));
    }
    for (int i = tid; i < 1024; i += 256) {          // WqT pairs
        int j = i >> 4, h4 = i & 15, h = h4 * 4;
        float a0 = aw[(h + 0) * 64 + j], a1 = aw[(h + 1) * 64 + j];
        float a2 = aw[(h + 2) * 64 + j], a3 = aw[(h + 3) * 64 + j];
        g_WqTp[((size_t)pair * 64 + j) * 16 + h4] = make_ulonglong2(pk(a0, a1), pk(a2, a3));
    }
}

// ---------------------------------------------------------------------------
// LSTM: block = (bchunk of 8, feature, branch). 256 blocks, 256 threads.
// ---------------------------------------------------------------------------
__global__ __launch_bounds__(256, 2) void lstm_kernel(
    const float* __restrict__ wd_x, const float* __restrict__ rd_x,
    const float* __restrict__ wd_Wih, const float* __restrict__ wd_Whh,
    const float* __restrict__ wd_bih, const float* __restrict__ wd_bhh,
    const float* __restrict__ rd_Wih, const float* __restrict__ rd_Whh,
    const float* __restrict__ rd_bih, const float* __restrict__ rd_bhh)
{
    int bc = blockIdx.x, f = blockIdx.y, br = blockIdx.z;
    int bBase = bc * 8;
    const float* x   = br ? rd_x   : wd_x;
    const float* Wih = br ? rd_Wih : wd_Wih;
    const float* Whh = br ? rd_Whh : wd_Whh;
    const float* bih = br ? rd_bih : wd_bih;
    const float* bhh = br ? rd_bhh : wd_bhh;

    __shared__ __align__(16) float h_s[64 * 8];
    __shared__ __align__(16) float c_s[64 * 8];
    __shared__ __align__(16) float gates_s[256 * 8];
    __shared__ __align__(16) float x_s[128 * 8];

    int tid = threadIdx.x;
    for (int i = tid; i < 128 * 8; i += 256) {
        int t = i >> 3, b = i & 7;
        x_s[i] = x[(size_t)(bBase + b) * Ssz * Fdim + t * Fdim + f];
    }
    for (int i = tid; i < 64 * 8; i += 256) { h_s[i] = 0.f; c_s[i] = 0.f; }

    int g = tid;
    float wih  = Wih[f * 256 + g];
    float bias = bih[f * 256 + g] + bhh[f * 256 + g];
    u64 wih2 = pk(wih, wih), bias2 = pk(bias, bias);

    float w[64];
#pragma unroll
    for (int j = 0; j < 64; j += 4) {
        float4 v = *(const float4*)&Whh[((size_t)f * 256 + g) * 64 + j];
        w[j] = v.x; w[j + 1] = v.y; w[j + 2] = v.z; w[j + 3] = v.w;
    }
    __syncthreads();

    for (int t = 0; t < Ssz; t++) {
        u64 acc0, acc1, acc2, acc3;
        {
            const u64* xp = (const u64*)&x_s[t * 8];
            acc0 = fma2(wih2, xp[0], bias2);
            acc1 = fma2(wih2, xp[1], bias2);
            acc2 = fma2(wih2, xp[2], bias2);
            acc3 = fma2(wih2, xp[3], bias2);
        }
#pragma unroll
        for (int j = 0; j < 64; j++) {
            u64 w2 = pk(w[j], w[j]);
            const ulonglong2* hp = (const ulonglong2*)&h_s[j * 8];
            ulonglong2 hA = hp[0], hB = hp[1];
            acc0 = fma2(w2, hA.x, acc0); acc1 = fma2(w2, hA.y, acc1);
            acc2 = fma2(w2, hB.x, acc2); acc3 = fma2(w2, hB.y, acc3);
        }
        ulonglong2* gp = (ulonglong2*)&gates_s[g * 8];
        gp[0] = make_ulonglong2(acc0, acc1);
        gp[1] = make_ulonglong2(acc2, acc3);
        __syncthreads();
        {
            int k = tid & 63, bg = tid >> 6;  // bg handles batches bg*2, bg*2+1
            float2 iv = *(const float2*)&gates_s[k * 8 + bg * 2];
            float2 fv = *(const float2*)&gates_s[(64 + k) * 8 + bg * 2];
            float2 gv = *(const float2*)&gates_s[(128 + k) * 8 + bg * 2];
            float2 ov = *(const float2*)&gates_s[(192 + k) * 8 + bg * 2];
            float2 cv = *(const float2*)&c_s[k * 8 + bg * 2];
            float2 cn, hn;
            cn.x = sigm(fv.x) * cv.x + sigm(iv.x) * tanh_(gv.x); hn.x = sigm(ov.x) * tanh_(cn.x);
            cn.y = sigm(fv.y) * cv.y + sigm(iv.y) * tanh_(gv.y); hn.y = sigm(ov.y) * tanh_(cn.y);
            *(float2*)&c_s[k * 8 + bg * 2] = cn;
            *(float2*)&h_s[k * 8 + bg * 2] = hn;
            size_t gb = ((((size_t)br * Bsz + bBase + bg * 2) * Fdim + f) * Ssz + t) * Hdim + k;
            const size_t bs = (size_t)Fdim * Ssz * Hdim;
            g_lstm[gb] = hn.x; g_lstm[gb + bs] = hn.y;
        }
        __syncthreads();
    }
}

// ---------------------------------------------------------------------------
// Attention (fused, V-projection eliminated): block per (f,b,branch), 256 thr.
// smem: xT [64][132] + kT [64][132] + small  => ~69 KB => 3 blocks/SM.
// ---------------------------------------------------------------------------
#define XPAD 132
#define ATTN_SMEM_FLOATS (64 * XPAD + 64 * XPAD + 256 + 128 + 64)

__global__ __launch_bounds__(256, 3) void attn_kernel(
    const float* __restrict__ wd_aw, const float* __restrict__ wd_ab,
    const float* __restrict__ wd_ow, const float* __restrict__ wd_ob,
    const float* __restrict__ rd_aw, const float* __restrict__ rd_ab,
    const float* __restrict__ rd_ow, const float* __restrict__ rd_ob,
    float* __restrict__ d_out)
{
    int f = blockIdx.x, b = blockIdx.y, br = blockIdx.z;
    const float* aw = br ? rd_aw : wd_aw;
    const float* ab = br ? rd_ab : wd_ab;
    const float* ow = br ? rd_ow : wd_ow;
    const float* ob = br ? rd_ob : wd_ob;

    extern __shared__ __align__(16) float sm[];
    float* xT     = sm;                    // [64][XPAD]
    float* kT     = sm + 64 * XPAD;        // [64][XPAD]
    float* wbar_s = kT + 64 * XPAD;        // [2][128]
    float* xw     = wbar_s + 256;          // [2][64]
    float* o_mean = xw + 128;              // [64]

    int tid = threadIdx.x, lane = tid & 31, warp = tid >> 5;
    int pairW = br * Fdim + f;                              // weight pair idx
    size_t pq = ((size_t)(br * Bsz + b) * Fdim + f);        // per-(br,b,f) idx

    // load x transposed
    const float* xsrc = g_lstm + pq * Ssz * Hdim;
    for (int i = tid * 4; i < Ssz * Hdim; i += 1024) {
        int s = i >> 6, h = i & 63;
        float4 v = *(const float4*)&xsrc[i];
        xT[(h + 0) * XPAD + s] = v.x; xT[(h + 1) * XPAD + s] = v.y;
        xT[(h + 2) * XPAD + s] = v.z; xT[(h + 3) * XPAD + s] = v.w;
    }
    if (tid < 256) wbar_s[tid] = 0.f;
    __syncthreads();

    // ---- k projection: warp-striped rows, dup-packed weights ----
    for (int r = 0; r < 8; r++) {
        int dk = warp * 8 + r;
        float bk = ab[f * 192 + 64 + dk];
        u64 a0 = pk(bk, bk), a1 = a0;
        const ulonglong2* wp = &g_w2k2[((size_t)pairW * 64 + dk) * 32];
#pragma unroll
        for (int j2 = 0; j2 < 32; j2++) {
            ulonglong2 w2 = wp[j2];
            ulonglong2 xv0 = *(const ulonglong2*)&xT[(2 * j2) * XPAD + lane * 4];
            ulonglong2 xv1 = *(const ulonglong2*)&xT[(2 * j2 + 1) * XPAD + lane * 4];
            a0 = fma2(w2.x, xv0.x, a0); a1 = fma2(w2.x, xv0.y, a1);
            a0 = fma2(w2.y, xv1.x, a0); a1 = fma2(w2.y, xv1.y, a1);
        }
        *(ulonglong2*)&kT[dk * XPAD + lane * 4] = make_ulonglong2(a0, a1);
    }

    // ---- q projection into global scratch: lane = (m=l>>1 -> qi, hq=l&1) ----
    {
        int m = lane >> 1, hq = lane & 1;
        int qi = warp + 8 * m;
#pragma unroll
        for (int p = 0; p < 2; p++) {
            int h0 = p * 32 + hq * 16;
            u64 acc[8];
            const ulonglong2* bp = (const ulonglong2*)&ab[f * 192 + h0];
#pragma unroll
            for (int i = 0; i < 4; i++) {
                ulonglong2 bb = bp[i];
                acc[2 * i] = bb.x; acc[2 * i + 1] = bb.y;
            }
            const ulonglong2* wbase = &g_WqTp[(size_t)pairW * 64 * 16 + (h0 >> 2)];
#pragma unroll
            for (int j = 0; j < 64; j++) {
                float xv = xT[j * XPAD + qi];
                u64 x2 = pk(xv, xv);
                const ulonglong2* wp = wbase + j * 16;
#pragma unroll
                for (int i = 0; i < 4; i++) {
                    ulonglong2 w2 = wp[i];
                    acc[2 * i]     = fma2(x2, w2.x, acc[2 * i]);
                    acc[2 * i + 1] = fma2(x2, w2.y, acc[2 * i + 1]);
                }
            }
            float4* qdst = &g_qsc4[pq * 2048 + (size_t)qi * 16 + (h0 >> 2)];
#pragma unroll
            for (int i = 0; i < 4; i++)
                *(ulonglong2*)&qdst[i] = make_ulonglong2(acc[2 * i], acc[2 * i + 1]);
        }
    }
    __syncthreads();

    // ---- scores + softmax + write attn weights + wbar ----
    const float scale = 0.17677669529663688f;  // 1/sqrt(32)
    float wbar_reg[8] = {0, 0, 0, 0, 0, 0, 0, 0};
    float* wout_base = d_out + 128 + (size_t)br * ((size_t)Fdim * Bsz * Ssz * Ssz)
                     + (((size_t)f * Bsz + b) * Ssz) * Ssz;
    const float4* qrow_base = &g_qsc4[pq * 2048];

    for (int m = 0; m < 16; m++) {
        int qi = warp + 8 * m;
        u64 a[2][2];
#pragma unroll
        for (int n = 0; n < 2; n++) {
            u64 a0 = 0ull, a1 = 0ull;
#pragma unroll
            for (int d4 = 0; d4 < 8; d4++) {
                float4 qf = __ldg(&qrow_base[(size_t)qi * 16 + n * 8 + d4]);
                u64 q0 = pk(qf.x, qf.x), q1 = pk(qf.y, qf.y);
                u64 q2 = pk(qf.z, qf.z), q3 = pk(qf.w, qf.w);
                int d = n * 32 + d4 * 4;
                ulonglong2 k0 = *(const ulonglong2*)&kT[(d + 0) * XPAD + lane * 4];
                ulonglong2 k1 = *(const ulonglong2*)&kT[(d + 1) * XPAD + lane * 4];
                ulonglong2 k2 = *(const ulonglong2*)&kT[(d + 2) * XPAD + lane * 4];
                ulonglong2 k3 = *(const ulonglong2*)&kT[(d + 3) * XPAD + lane * 4];
                a0 = fma2(q0, k0.x, a0); a1 = fma2(q0, k0.y, a1);
                a0 = fma2(q1, k1.x, a0); a1 = fma2(q1, k1.y, a1);
                a0 = fma2(q2, k2.x, a0); a1 = fma2(q2, k2.y, a1);
                a0 = fma2(q3, k3.x, a0); a1 = fma2(q3, k3.y, a1);
            }
            a[n][0] = a0; a[n][1] = a1;
        }
        float wv[2][4];
#pragma unroll
        for (int n = 0; n < 2; n++) {
            float2 p0 = upk(a[n][0]), p1 = upk(a[n][1]);
            float s0 = p0.x * scale, s1 = p0.y * scale;
            float s2 = p1.x * scale, s3 = p1.y * scale;
            float mx = fmaxf(fmaxf(s0, s1), fmaxf(s2, s3));
#pragma unroll
            for (int off = 16; off > 0; off >>= 1)
                mx = fmaxf(mx, __shfl_xor_sync(0xffffffffu, mx, off));
            float e0 = __expf(s0 - mx), e1 = __expf(s1 - mx);
            float e2 = __expf(s2 - mx), e3 = __expf(s3 - mx);
            float sum = e0 + e1 + e2 + e3;
#pragma unroll
            for (int off = 16; off > 0; off >>= 1)
                sum += __shfl_xor_sync(0xffffffffu, sum, off);
            float inv = __fdividef(1.f, sum);
            wv[n][0] = e0 * inv; wv[n][1] = e1 * inv;
            wv[n][2] = e2 * inv; wv[n][3] = e3 * inv;
            wbar_reg[n * 4 + 0] += wv[n][0]; wbar_reg[n * 4 + 1] += wv[n][1];
            wbar_reg[n * 4 + 2] += wv[n][2]; wbar_reg[n * 4 + 3] += wv[n][3];
        }
        float4 o4;
        o4.x = 0.5f * (wv[0][0] + wv[1][0]); o4.y = 0.5f * (wv[0][1] + wv[1][1]);
        o4.z = 0.5f * (wv[0][2] + wv[1][2]); o4.w = 0.5f * (wv[0][3] + wv[1][3]);
        *(float4*)&wout_base[(size_t)qi * Ssz + lane * 4] = o4;
    }
#pragma unroll
    for (int n = 0; n < 2; n++)
#pragma unroll
        for (int i = 0; i < 4; i++)
            atomicAdd(&wbar_s[n * 128 + lane * 4 + i], wbar_reg[n * 4 + i]);
    __syncthreads();

    // ---- epilogue: xw = wbar @ x ; o_mean = Wv@xw + bv ; pooled ----
    if (tid < 128) {
        int n = tid >> 6, j = tid & 63;
        float a = 0.f;
        for (int k = 0; k < 128; k++)
            a += wbar_s[n * 128 + k] * xT[j * XPAD + k];
        xw[tid] = a * (1.f / 128.f);
    }
    __syncthreads();
    if (tid < 64) {
        int h = tid, n = h >> 5;
        float a = ab[f * 192 + 128 + h];
        const float* wvp = aw + (size_t)f * 192 * 64 + (128 + h) * 64;
        for (int j = 0; j < 64; j++) a += wvp[j] * xw[n * 64 + j];
        o_mean[h] = a;
    }
    __syncthreads();
    if (tid < 64) {
        float a = ob[f * 64 + tid];
        const float* wrow = ow + ((size_t)f * 64 + tid) * 64;
        for (int h = 0; h < 64; h++) a += o_mean[h] * wrow[h];
        g_pooled[(((size_t)br * Bsz + b) * Fdim + f) * 64 + tid] = a;
    }
}

// ---------------------------------------------------------------------------
// Final: static DNN + time module + FC.
// ---------------------------------------------------------------------------
__global__ __launch_bounds__(128) void final_kernel(
    const float* __restrict__ statin, const float* __restrict__ tg,
    const float* __restrict__ d1w, const float* __restrict__ d1b,
    const float* __restrict__ d2w, const float* __restrict__ d2b,
    const float* __restrict__ t1w, const float* __restrict__ t1b,
    const float* __restrict__ t2w, const float* __restrict__ t2b,
    const float* __restrict__ fcw, const float* __restrict__ fcb,
    float* __restrict__ out)
{
    __shared__ float s1[64], sf[32], t1v[16], tf[8], red[128];
    int b = blockIdx.x, tid = threadIdx.x;
    if (tid < 64) {
        float a = d1b[tid];
        for (int i = 0; i < 32; i++) a += statin[b * 32 + i] * d1w[tid * 32 + i];
        s1[tid] = fmaxf(a, 0.f);
    }
    if (tid < 16) t1v[tid] = fmaxf(t1b[tid] + tg[b] * t1w[tid], 0.f);
    __syncthreads();
    if (tid < 32) {
        float a = d2b[tid];
        for (int i = 0; i < 64; i++) a += s1[i] * d2w[tid * 64 + i];
        sf[tid] = fmaxf(a, 0.f);
    }
    if (tid < 8) {
        float a = t2b[tid];
        for (int i = 0; i < 16; i++) a += t1v[i] * t2w[tid * 16 + i];
        tf[tid] = fmaxf(a, 0.f);
    }
    __syncthreads();
    for (int o = 0; o < 2; o++) {
        float a = 0.f;
        for (int i = tid; i < 2088; i += 128) {
            float cv;
            if (i < 1024)      cv = g_pooled[(size_t)b * 1024 + i];
            else if (i < 2048) cv = g_pooled[(size_t)(Bsz + b) * 1024 + (i - 1024)];
            else if (i < 2080) cv = sf[i - 2048];
            else               cv = tf[i - 2080];
            a += cv * fcw[o * 2088 + i];
        }
        red[tid] = a;
        __syncthreads();
        for (int st = 64; st > 0; st >>= 1) {
            if (tid < st) red[tid] += red[tid + st];
            __syncthreads();
        }
        if (tid == 0) out[b * 2 + o] = red[0] + fcb[o];
        __syncthreads();
    }
}

extern "C" void kernel_launch(void* const* d_in, const int* in_sizes, int n_in,
                              void* d_out, int out_size)
{
    const float* wd_x    = (const float*)d_in[0];
    const float* rd_x    = (const float*)d_in[1];
    const float* statin  = (const float*)d_in[2];
    const float* tg      = (const float*)d_in[3];
    const float* wd_Wih  = (const float*)d_in[4];
    const float* wd_Whh  = (const float*)d_in[5];
    const float* wd_bih  = (const float*)d_in[6];
    const float* wd_bhh  = (const float*)d_in[7];
    const float* rd_Wih  = (const float*)d_in[8];
    const float* rd_Whh  = (const float*)d_in[9];
    const float* rd_bih  = (const float*)d_in[10];
    const float* rd_bhh  = (const float*)d_in[11];
    const float* wd_aw   = (const float*)d_in[12];
    const float* wd_ab   = (const float*)d_in[13];
    const float* wd_ow   = (const float*)d_in[14];
    const float* wd_ob   = (const float*)d_in[15];
    const float* rd_aw   = (const float*)d_in[16];
    const float* rd_ab   = (const float*)d_in[17];
    const float* rd_ow   = (const float*)d_in[18];
    const float* rd_ob   = (const float*)d_in[19];
    const float* d1w     = (const float*)d_in[20];
    const float* d1b     = (const float*)d_in[21];
    const float* d2w     = (const float*)d_in[22];
    const float* d2b     = (const float*)d_in[23];
    const float* t1w     = (const float*)d_in[24];
    const float* t1b     = (const float*)d_in[25];
    const float* t2w     = (const float*)d_in[26];
    const float* t2b     = (const float*)d_in[27];
    const float* fcw     = (const float*)d_in[28];
    const float* fcb     = (const float*)d_in[29];
    float* out = (float*)d_out;

    cudaFuncSetAttribute(attn_kernel, cudaFuncAttributeMaxDynamicSharedMemorySize,
                         ATTN_SMEM_FLOATS * 4);

    prep_kernel<<<dim3(Fdim, 2), 256>>>(wd_aw, rd_aw);

    lstm_kernel<<<dim3(8, Fdim, 2), 256>>>(
        wd_x, rd_x, wd_Wih, wd_Whh, wd_bih, wd_bhh, rd_Wih, rd_Whh, rd_bih, rd_bhh);

    attn_kernel<<<dim3(Fdim, Bsz, 2), 256, ATTN_SMEM_FLOATS * 4>>>(
        wd_aw, wd_ab, wd_ow, wd_ob, rd_aw, rd_ab, rd_ow, rd_ob, out);

    final_kernel<<<Bsz, 128>>>(
        statin, tg, d1w, d1b, d2w, d2b, t1w, t1b, t2w, t2b, fcw, fcb, out);
}

// round 3
// speedup vs baseline: 1.4186x; 1.4186x over previous
#include <cuda_runtime.h>

#define Bsz 64
#define Ssz 128
#define Fdim 16
#define Hdim 64
#define XPAD 132
#define SCALE 0.17677669529663688f

typedef unsigned long long u64;

__device__ __forceinline__ u64 pk(float a, float b) {
    u64 r; asm("mov.b64 %0, {%1,%2};" : "=l"(r) : "f"(a), "f"(b)); return r;
}
__device__ __forceinline__ u64 fma2(u64 a, u64 b, u64 c) {
    u64 d; asm("fma.rn.f32x2 %0, %1, %2, %3;" : "=l"(d) : "l"(a), "l"(b), "l"(c)); return d;
}
__device__ __forceinline__ float2 upk(u64 v) {
    float2 r; asm("mov.b64 {%0,%1}, %2;" : "=f"(r.x), "=f"(r.y) : "l"(v)); return r;
}
__device__ __forceinline__ float sigm(float x) { return __fdividef(1.f, 1.f + __expf(-x)); }
__device__ __forceinline__ float tanh_(float x) { return 1.f - __fdividef(2.f, __expf(2.f * x) + 1.f); }

// scratch
__device__ float g_lstm[2u * Bsz * Fdim * Ssz * Hdim];   // [br][b][f][s][h]
__device__ float g_pooled[2u * Bsz * Fdim * Hdim];
__device__ ulonglong2 g_w2p[32 * 128 * 32];              // dup-packed qk weights [pair][row][j2]
__device__ float g_WvT[32 * 64 * 64];                    // [pair][j][h]
__device__ float g_WoT[32 * 64 * 64];                    // [pair][h][o]

// ---------------------------------------------------------------------------
// Prep: pre-transform attention weights (tiny, runs once per launch).
// ---------------------------------------------------------------------------
__global__ void prep_kernel(const float* __restrict__ wd_aw, const float* __restrict__ rd_aw,
                            const float* __restrict__ wd_ow, const float* __restrict__ rd_ow)
{
    int f = blockIdx.x, br = blockIdx.y, tid = threadIdx.x;
    const float* aw = (br ? rd_aw : wd_aw) + (size_t)f * 192 * 64;
    const float* ow = (br ? rd_ow : wd_ow) + (size_t)f * 64 * 64;
    int pair = br * Fdim + f;
    for (int i = tid; i < 128 * 32; i += 256) {
        int row = i >> 5, j2 = i & 31;
        float sc = (row < 64) ? SCALE : 1.f;
        float w0 = aw[row * 64 + 2 * j2] * sc;
        float w1 = aw[row * 64 + 2 * j2 + 1] * sc;
        g_w2p[((size_t)pair * 128 + row) * 32 + j2] = make_ulonglong2(pk(w0, w0), pk(w1, w1));
    }
    for (int i = tid; i < 4096; i += 256) {
        int j = i >> 6, h = i & 63;
        g_WvT[(size_t)pair * 4096 + j * 64 + h] = aw[(128 + h) * 64 + j];
    }
    for (int i = tid; i < 4096; i += 256) {
        int h = i >> 6, o = i & 63;
        g_WoT[(size_t)pair * 4096 + h * 64 + o] = ow[o * 64 + h];
    }
}

// ---------------------------------------------------------------------------
// LSTM: block = (bchunk of 8, feature, branch). 256 blocks, 256 threads.
// ---------------------------------------------------------------------------
__global__ __launch_bounds__(256, 2) void lstm_kernel(
    const float* __restrict__ wd_x, const float* __restrict__ rd_x,
    const float* __restrict__ wd_Wih, const float* __restrict__ wd_Whh,
    const float* __restrict__ wd_bih, const float* __restrict__ wd_bhh,
    const float* __restrict__ rd_Wih, const float* __restrict__ rd_Whh,
    const float* __restrict__ rd_bih, const float* __restrict__ rd_bhh)
{
    int bc = blockIdx.x, f = blockIdx.y, br = blockIdx.z;
    int bBase = bc * 8;
    const float* x   = br ? rd_x   : wd_x;
    const float* Wih = br ? rd_Wih : wd_Wih;
    const float* Whh = br ? rd_Whh : wd_Whh;
    const float* bih = br ? rd_bih : wd_bih;
    const float* bhh = br ? rd_bhh : wd_bhh;

    __shared__ __align__(16) float h_s[64 * 8];
    __shared__ __align__(16) float c_s[64 * 8];
    __shared__ __align__(16) float gates_s[256 * 8];
    __shared__ __align__(16) float x_s[128 * 8];

    int tid = threadIdx.x;
    for (int i = tid; i < 128 * 8; i += 256) {
        int t = i >> 3, b = i & 7;
        x_s[i] = x[(size_t)(bBase + b) * Ssz * Fdim + t * Fdim + f];
    }
    for (int i = tid; i < 64 * 8; i += 256) { h_s[i] = 0.f; c_s[i] = 0.f; }

    int g = tid;
    float wih  = Wih[f * 256 + g];
    float bias = bih[f * 256 + g] + bhh[f * 256 + g];
    u64 wih2 = pk(wih, wih), bias2 = pk(bias, bias);

    float w[64];
#pragma unroll
    for (int j = 0; j < 64; j += 4) {
        float4 v = *(const float4*)&Whh[((size_t)f * 256 + g) * 64 + j];
        w[j] = v.x; w[j + 1] = v.y; w[j + 2] = v.z; w[j + 3] = v.w;
    }
    __syncthreads();

    for (int t = 0; t < Ssz; t++) {
        u64 acc0, acc1, acc2, acc3;
        {
            const u64* xp = (const u64*)&x_s[t * 8];
            acc0 = fma2(wih2, xp[0], bias2);
            acc1 = fma2(wih2, xp[1], bias2);
            acc2 = fma2(wih2, xp[2], bias2);
            acc3 = fma2(wih2, xp[3], bias2);
        }
#pragma unroll
        for (int j = 0; j < 64; j++) {
            u64 w2 = pk(w[j], w[j]);
            const ulonglong2* hp = (const ulonglong2*)&h_s[j * 8];
            ulonglong2 hA = hp[0], hB = hp[1];
            acc0 = fma2(w2, hA.x, acc0); acc1 = fma2(w2, hA.y, acc1);
            acc2 = fma2(w2, hB.x, acc2); acc3 = fma2(w2, hB.y, acc3);
        }
        ulonglong2* gp = (ulonglong2*)&gates_s[g * 8];
        gp[0] = make_ulonglong2(acc0, acc1);
        gp[1] = make_ulonglong2(acc2, acc3);
        __syncthreads();
        {
            int k = tid & 63, bg = tid >> 6;
            float2 iv = *(const float2*)&gates_s[k * 8 + bg * 2];
            float2 fv = *(const float2*)&gates_s[(64 + k) * 8 + bg * 2];
            float2 gv = *(const float2*)&gates_s[(128 + k) * 8 + bg * 2];
            float2 ov = *(const float2*)&gates_s[(192 + k) * 8 + bg * 2];
            float2 cv = *(const float2*)&c_s[k * 8 + bg * 2];
            float2 cn, hn;
            cn.x = sigm(fv.x) * cv.x + sigm(iv.x) * tanh_(gv.x); hn.x = sigm(ov.x) * tanh_(cn.x);
            cn.y = sigm(fv.y) * cv.y + sigm(iv.y) * tanh_(gv.y); hn.y = sigm(ov.y) * tanh_(cn.y);
            *(float2*)&c_s[k * 8 + bg * 2] = cn;
            *(float2*)&h_s[k * 8 + bg * 2] = hn;
            size_t gb = ((((size_t)br * Bsz + bBase + bg * 2) * Fdim + f) * Ssz + t) * Hdim + k;
            const size_t bs = (size_t)Fdim * Ssz * Hdim;
            g_lstm[gb] = hn.x; g_lstm[gb + bs] = hn.y;
        }
        __syncthreads();
    }
}

// ---------------------------------------------------------------------------
// Attention (fused, V eliminated): block per (f,b,branch), 256 threads.
// smem = xT + qkT + partials = ~111 KB  => 2 blocks/SM.
// ---------------------------------------------------------------------------
#define ATTN_SMEM_FLOATS (64 * XPAD + 128 * XPAD + 2048 + 256 + 128 + 64)

__global__ __launch_bounds__(256, 2) void attn_kernel(
    const float* __restrict__ wd_aw, const float* __restrict__ wd_ab,
    const float* __restrict__ wd_ob,
    const float* __restrict__ rd_aw, const float* __restrict__ rd_ab,
    const float* __restrict__ rd_ob,
    float* __restrict__ d_out)
{
    int f = blockIdx.x, b = blockIdx.y, br = blockIdx.z;
    const float* ab = br ? rd_ab : wd_ab;
    const float* ob = br ? rd_ob : wd_ob;

    extern __shared__ __align__(16) float sm[];
    float* xT        = sm;                      // [64][XPAD]
    float* qkT       = sm + 64 * XPAD;          // [128][XPAD]  rows 0-63 q (pre-scaled), 64-127 k
    float* wbar_part = qkT + 128 * XPAD;        // [8 warps][2 heads][128]
    float* wbar_s    = wbar_part + 2048;        // [2][128]
    float* xw        = wbar_s + 256;            // [2][64]
    float* o_mean    = xw + 128;                // [64]

    int tid = threadIdx.x, lane = tid & 31, warp = tid >> 5;
    int pairW = br * Fdim + f;
    size_t pq = ((size_t)(br * Bsz + b) * Fdim + f);

    // load x transposed: xT[h][s]
    const float* xsrc = g_lstm + pq * Ssz * Hdim;
    for (int i = tid * 4; i < Ssz * Hdim; i += 1024) {
        int s = i >> 6, h = i & 63;
        float4 v = *(const float4*)&xsrc[i];
        xT[(h + 0) * XPAD + s] = v.x; xT[(h + 1) * XPAD + s] = v.y;
        xT[(h + 2) * XPAD + s] = v.z; xT[(h + 3) * XPAD + s] = v.w;
    }
    __syncthreads();

    // ---- phase 1: q+k projection (128 rows, transposed output) ----
    for (int r = 0; r < 16; r++) {
        int row = warp * 16 + r;
        float bb = ab[f * 192 + row] * ((row < 64) ? SCALE : 1.f);
        u64 a0 = pk(bb, bb), a1 = a0;
        const ulonglong2* wp = &g_w2p[((size_t)pairW * 128 + row) * 32];
#pragma unroll
        for (int j2 = 0; j2 < 32; j2++) {
            ulonglong2 w2 = __ldg(&wp[j2]);
            ulonglong2 x0 = *(const ulonglong2*)&xT[(2 * j2) * XPAD + lane * 4];
            ulonglong2 x1 = *(const ulonglong2*)&xT[(2 * j2 + 1) * XPAD + lane * 4];
            a0 = fma2(w2.x, x0.x, a0); a1 = fma2(w2.x, x0.y, a1);
            a0 = fma2(w2.y, x1.x, a0); a1 = fma2(w2.y, x1.y, a1);
        }
        *(ulonglong2*)&qkT[row * XPAD + lane * 4] = make_ulonglong2(a0, a1);
    }
    __syncthreads();

    // ---- phase 2: scores + softmax + attn-weight write + wbar ----
    float wbar_reg[8] = {0, 0, 0, 0, 0, 0, 0, 0};
    float* wout_base = d_out + 128 + (size_t)br * ((size_t)Fdim * Bsz * Ssz * Ssz)
                     + (((size_t)f * Bsz + b) * Ssz) * Ssz;

#pragma unroll 1
    for (int m = 0; m < 4; m++) {
        int qi0 = (warp << 4) + (m << 2);
        float wvv[2][16];
#pragma unroll
        for (int n = 0; n < 2; n++) {
            u64 acc[8];
#pragma unroll
            for (int i = 0; i < 8; i++) acc[i] = 0ull;
#pragma unroll
            for (int d = 0; d < 32; d++) {
                int hg = (n << 5) + d;
                float4 qf = *(const float4*)&qkT[hg * XPAD + qi0];
                ulonglong2 kv = *(const ulonglong2*)&qkT[(64 + hg) * XPAD + lane * 4];
                u64 q0 = pk(qf.x, qf.x), q1 = pk(qf.y, qf.y);
                u64 q2 = pk(qf.z, qf.z), q3 = pk(qf.w, qf.w);
                acc[0] = fma2(q0, kv.x, acc[0]); acc[1] = fma2(q0, kv.y, acc[1]);
                acc[2] = fma2(q1, kv.x, acc[2]); acc[3] = fma2(q1, kv.y, acc[3]);
                acc[4] = fma2(q2, kv.x, acc[4]); acc[5] = fma2(q2, kv.y, acc[5]);
                acc[6] = fma2(q3, kv.x, acc[6]); acc[7] = fma2(q3, kv.y, acc[7]);
            }
#pragma unroll
            for (int v = 0; v < 4; v++) {
                float2 p0 = upk(acc[2 * v]), p1 = upk(acc[2 * v + 1]);
                float s0 = p0.x, s1 = p0.y, s2 = p1.x, s3 = p1.y;
                float mx = fmaxf(fmaxf(s0, s1), fmaxf(s2, s3));
#pragma unroll
                for (int off = 16; off > 0; off >>= 1)
                    mx = fmaxf(mx, __shfl_xor_sync(0xffffffffu, mx, off));
                float e0 = __expf(s0 - mx), e1 = __expf(s1 - mx);
                float e2 = __expf(s2 - mx), e3 = __expf(s3 - mx);
                float sum = e0 + e1 + e2 + e3;
#pragma unroll
                for (int off = 16; off > 0; off >>= 1)
                    sum += __shfl_xor_sync(0xffffffffu, sum, off);
                float inv = __fdividef(1.f, sum);
                e0 *= inv; e1 *= inv; e2 *= inv; e3 *= inv;
                wvv[n][v * 4 + 0] = e0; wvv[n][v * 4 + 1] = e1;
                wvv[n][v * 4 + 2] = e2; wvv[n][v * 4 + 3] = e3;
                wbar_reg[n * 4 + 0] += e0; wbar_reg[n * 4 + 1] += e1;
                wbar_reg[n * 4 + 2] += e2; wbar_reg[n * 4 + 3] += e3;
            }
        }
#pragma unroll
        for (int v = 0; v < 4; v++) {
            float4 o4;
            o4.x = 0.5f * (wvv[0][v * 4 + 0] + wvv[1][v * 4 + 0]);
            o4.y = 0.5f * (wvv[0][v * 4 + 1] + wvv[1][v * 4 + 1]);
            o4.z = 0.5f * (wvv[0][v * 4 + 2] + wvv[1][v * 4 + 2]);
            o4.w = 0.5f * (wvv[0][v * 4 + 3] + wvv[1][v * 4 + 3]);
            *(float4*)&wout_base[(size_t)(qi0 + v) * Ssz + lane * 4] = o4;
        }
    }
    *(float4*)&wbar_part[(warp * 2 + 0) * 128 + lane * 4] =
        make_float4(wbar_reg[0], wbar_reg[1], wbar_reg[2], wbar_reg[3]);
    *(float4*)&wbar_part[(warp * 2 + 1) * 128 + lane * 4] =
        make_float4(wbar_reg[4], wbar_reg[5], wbar_reg[6], wbar_reg[7]);
    __syncthreads();

    // ---- epilogue ----
    {   // wbar_s[n][k] = (1/S) * sum over warps
        int n = tid >> 7, k = tid & 127;
        float a = 0.f;
#pragma unroll
        for (int wpi = 0; wpi < 8; wpi++) a += wbar_part[(wpi * 2 + n) * 128 + k];
        wbar_s[n * 128 + k] = a * (1.f / 128.f);
    }
    __syncthreads();
    if (tid < 128) {   // xw[n][j] = sum_k wbar_s[n][k] * x[k][j]
        int n = tid >> 6, j = tid & 63;
        float a = 0.f;
        for (int k = 0; k < 128; k++)
            a += wbar_s[n * 128 + k] * xT[j * XPAD + k];
        xw[tid] = a;
    }
    __syncthreads();
    if (tid < 64) {    // o_mean[h] = bv[h] + sum_j WvT[j][h] * xw[head(h)][j]
        int h = tid, n = h >> 5;
        float a = ab[f * 192 + 128 + h];
        const float* wvp = g_WvT + (size_t)pairW * 4096;
        for (int j = 0; j < 64; j++) a += wvp[j * 64 + h] * xw[n * 64 + j];
        o_mean[h] = a;
    }
    __syncthreads();
    if (tid < 64) {    // pooled[o] = ob[o] + sum_h WoT[h][o] * o_mean[h]
        int o = tid;
        float a = ob[f * 64 + o];
        const float* wop = g_WoT + (size_t)pairW * 4096;
        for (int h = 0; h < 64; h++) a += wop[h * 64 + o] * o_mean[h];
        g_pooled[(((size_t)br * Bsz + b) * Fdim + f) * 64 + o] = a;
    }
}

// ---------------------------------------------------------------------------
// Final: static DNN + time module + FC.
// ---------------------------------------------------------------------------
__global__ __launch_bounds__(128) void final_kernel(
    const float* __restrict__ statin, const float* __restrict__ tg,
    const float* __restrict__ d1w, const float* __restrict__ d1b,
    const float* __restrict__ d2w, const float* __restrict__ d2b,
    const float* __restrict__ t1w, const float* __restrict__ t1b,
    const float* __restrict__ t2w, const float* __restrict__ t2b,
    const float* __restrict__ fcw, const float* __restrict__ fcb,
    float* __restrict__ out)
{
    __shared__ float s1[64], sf[32], t1v[16], tf[8], red[4];
    int b = blockIdx.x, tid = threadIdx.x;
    int lane = tid & 31, warp = tid >> 5;
    if (tid < 64) {
        float a = d1b[tid];
        for (int i = 0; i < 32; i++) a += statin[b * 32 + i] * d1w[tid * 32 + i];
        s1[tid] = fmaxf(a, 0.f);
    }
    if (tid < 16) t1v[tid] = fmaxf(t1b[tid] + tg[b] * t1w[tid], 0.f);
    __syncthreads();
    if (tid < 32) {
        float a = d2b[tid];
        for (int i = 0; i < 64; i++) a += s1[i] * d2w[tid * 64 + i];
        sf[tid] = fmaxf(a, 0.f);
    }
    if (tid < 8) {
        float a = t2b[tid];
        for (int i = 0; i < 16; i++) a += t1v[i] * t2w[tid * 16 + i];
        tf[tid] = fmaxf(a, 0.f);
    }
    __syncthreads();
    for (int o = 0; o < 2; o++) {
        float a = 0.f;
        for (int i = tid; i < 2088; i += 128) {
            float cv;
            if (i < 1024)      cv = g_pooled[(size_t)b * 1024 + i];
            else if (i < 2048) cv = g_pooled[(size_t)(Bsz + b) * 1024 + (i - 1024)];
            else if (i < 2080) cv = sf[i - 2048];
            else               cv = tf[i - 2080];
            a += cv * fcw[o * 2088 + i];
        }
#pragma unroll
        for (int off = 16; off > 0; off >>= 1)
            a += __shfl_xor_sync(0xffffffffu, a, off);
        if (lane == 0) red[warp] = a;
        __syncthreads();
        if (tid == 0) out[b * 2 + o] = red[0] + red[1] + red[2] + red[3] + fcb[o];
        __syncthreads();
    }
}

extern "C" void kernel_launch(void* const* d_in, const int* in_sizes, int n_in,
                              void* d_out, int out_size)
{
    const float* wd_x    = (const float*)d_in[0];
    const float* rd_x    = (const float*)d_in[1];
    const float* statin  = (const float*)d_in[2];
    const float* tg      = (const float*)d_in[3];
    const float* wd_Wih  = (const float*)d_in[4];
    const float* wd_Whh  = (const float*)d_in[5];
    const float* wd_bih  = (const float*)d_in[6];
    const float* wd_bhh  = (const float*)d_in[7];
    const float* rd_Wih  = (const float*)d_in[8];
    const float* rd_Whh  = (const float*)d_in[9];
    const float* rd_bih  = (const float*)d_in[10];
    const float* rd_bhh  = (const float*)d_in[11];
    const float* wd_aw   = (const float*)d_in[12];
    const float* wd_ab   = (const float*)d_in[13];
    const float* wd_ow   = (const float*)d_in[14];
    const float* wd_ob   = (const float*)d_in[15];
    const float* rd_aw   = (const float*)d_in[16];
    const float* rd_ab   = (const float*)d_in[17];
    const float* rd_ow   = (const float*)d_in[18];
    const float* rd_ob   = (const float*)d_in[19];
    const float* d1w     = (const float*)d_in[20];
    const float* d1b     = (const float*)d_in[21];
    const float* d2w     = (const float*)d_in[22];
    const float* d2b     = (const float*)d_in[23];
    const float* t1w     = (const float*)d_in[24];
    const float* t1b     = (const float*)d_in[25];
    const float* t2w     = (const float*)d_in[26];
    const float* t2b     = (const float*)d_in[27];
    const float* fcw     = (const float*)d_in[28];
    const float* fcb     = (const float*)d_in[29];
    float* out = (float*)d_out;

    cudaFuncSetAttribute(attn_kernel, cudaFuncAttributeMaxDynamicSharedMemorySize,
                         ATTN_SMEM_FLOATS * 4);

    prep_kernel<<<dim3(Fdim, 2), 256>>>(wd_aw, rd_aw, wd_ow, rd_ow);

    lstm_kernel<<<dim3(8, Fdim, 2), 256>>>(
        wd_x, rd_x, wd_Wih, wd_Whh, wd_bih, wd_bhh, rd_Wih, rd_Whh, rd_bih, rd_bhh);

    attn_kernel<<<dim3(Fdim, Bsz, 2), 256, ATTN_SMEM_FLOATS * 4>>>(
        wd_aw, wd_ab, wd_ob, rd_aw, rd_ab, rd_ob, out);

    final_kernel<<<Bsz, 128>>>(
        statin, tg, d1w, d1b, d2w, d2b, t1w, t1b, t2w, t2b, fcw, fcb, out);
}